// round 2
// baseline (speedup 1.0000x reference)
#include <cuda_runtime.h>

// Fused 3D windowed attention block, FFMA2 (f32x2) edition.
// One CTA per 4x4x4 window (4096 CTAs, 256 threads).
//
// SMEM (floats):
//   xs [64][132]  window input, later y_s (attention output)
//   qs [64][516]  per-row: [0:128) Q | [128:384) K duplicated (k,k) pairs | [384:512) V
//   wt [64][258]  weight tile as k-pair float2: wt[kp][2n..2n+1] = (W[n][2kp], W[n][2kp+1])

#define D0 30
#define H0 62
#define W0 126
#define MTOT (30*62*126)

#define XS_STRIDE 132
#define QS_STRIDE 516
#define WT_STRIDE 258
#define XS_OFF 0
#define QS_OFF (64*XS_STRIDE)                 // 8448
#define WT_OFF (QS_OFF + 64*QS_STRIDE)        // 41472
#define SMEM_FLOATS (WT_OFF + 64*WT_STRIDE)   // 57984 floats = 231936 B

typedef unsigned long long u64;

__device__ __forceinline__ u64 pack2(float a, float b) {
    u64 d;
    asm("mov.b64 %0, {%1, %2};" : "=l"(d) : "r"(__float_as_uint(a)), "r"(__float_as_uint(b)));
    return d;
}
__device__ __forceinline__ void unpack2(u64 v, float& a, float& b) {
    unsigned x, y;
    asm("mov.b64 {%0, %1}, %2;" : "=r"(x), "=r"(y) : "l"(v));
    a = __uint_as_float(x);
    b = __uint_as_float(y);
}
__device__ __forceinline__ u64 ffma2(u64 a, u64 b, u64 c) {
    u64 d;
    asm("fma.rn.f32x2 %0, %1, %2, %3;" : "=l"(d) : "l"(a), "l"(b), "l"(c));
    return d;
}
__device__ __forceinline__ u64 fmul2(u64 a, u64 b) {
    u64 d;
    asm("mul.rn.f32x2 %0, %1, %2;" : "=l"(d) : "l"(a), "l"(b));
    return d;
}

// Load a 128x128 row-major weight matrix into the k-pair float2 tile.
__device__ __forceinline__ void load_w(const float* __restrict__ W, float* __restrict__ Ws, int t) {
    #pragma unroll
    for (int it = 0; it < 16; ++it) {
        int idx = t + 256 * it;
        int o = idx >> 5;        // output row 0..127
        int q = idx & 31;        // float4 group 0..31
        float4 v = *(const float4*)(W + o * 128 + 4 * q);
        *(float2*)(Ws + (2 * q)     * WT_STRIDE + 2 * o) = make_float2(v.x, v.y);
        *(float2*)(Ws + (2 * q + 1) * WT_STRIDE + 2 * o) = make_float2(v.z, v.w);
    }
}

// 64x128x128 GEMM: out[row][n] = sum_k A[row][k] * W[n][k]
// rows: ty+16i (i<4), col pairs p: (tx+32p, tx+32p+16), acc in f32x2.
__device__ __forceinline__ void gemm64(const float* __restrict__ As, const float* __restrict__ Ws,
                                       int tx, int ty, u64 acc[4][4]) {
    #pragma unroll 4
    for (int kp = 0; kp < 64; ++kp) {
        const float* wrow = Ws + kp * WT_STRIDE;
        float2 b[8];
        #pragma unroll
        for (int m = 0; m < 8; ++m)
            b[m] = *(const float2*)(wrow + 2 * (tx + 16 * m));
        float2 a[4];
        #pragma unroll
        for (int i = 0; i < 4; ++i)
            a[i] = *(const float2*)(As + (ty + 16 * i) * XS_STRIDE + 2 * kp);

        u64 bk0[4], bk1[4];
        #pragma unroll
        for (int p = 0; p < 4; ++p) {
            bk0[p] = pack2(b[2 * p].x, b[2 * p + 1].x);   // k = 2kp
            bk1[p] = pack2(b[2 * p].y, b[2 * p + 1].y);   // k = 2kp+1
        }
        #pragma unroll
        for (int i = 0; i < 4; ++i) {
            u64 a0 = pack2(a[i].x, a[i].x);
            u64 a1 = pack2(a[i].y, a[i].y);
            #pragma unroll
            for (int p = 0; p < 4; ++p) {
                acc[i][p] = ffma2(a0, bk0[p], acc[i][p]);
                acc[i][p] = ffma2(a1, bk1[p], acc[i][p]);
            }
        }
    }
}

__global__ void __launch_bounds__(256, 1)
fused_window_attn_kernel(const float* __restrict__ x,
                         const float* __restrict__ qkv_w,
                         const float* __restrict__ qkv_b,
                         const float* __restrict__ conv_w,
                         const float* __restrict__ conv_b,
                         float* __restrict__ out)
{
    extern __shared__ float sm[];
    float* xs = sm + XS_OFF;
    float* qs = sm + QS_OFF;
    float* wt = sm + WT_OFF;

    const int t  = threadIdx.x;
    const int wi = blockIdx.x;
    const int bz = wi >> 9;
    const int by = (wi >> 5) & 15;
    const int bx = wi & 31;
    const int z0 = bz * 4, y0 = by * 4, x0 = bx * 4;

    // ---------------- phase 1: gather window ----------------
    #pragma unroll 4
    for (int idx = t; idx < 64 * 128; idx += 256) {
        int l = idx & 63;
        int c = idx >> 6;
        int gz = z0 + (l >> 4);
        int gy = y0 + ((l >> 2) & 3);
        int gx = x0 + (l & 3);
        float v = 0.f;
        if (gz < D0 && gy < H0 && gx < W0)
            v = x[((c * D0 + gz) * H0 + gy) * W0 + gx];
        xs[l * XS_STRIDE + c] = v;
    }

    const int tx = t & 15;
    const int ty = t >> 4;

    // ---------------- phase 2: QKV GEMM, 3 chunks (Q, Kdup, V) ----------------
    #pragma unroll 1
    for (int chunk = 0; chunk < 3; ++chunk) {
        __syncthreads();
        load_w(qkv_w + chunk * 128 * 128, wt, t);
        __syncthreads();

        u64 acc[4][4];
        #pragma unroll
        for (int i = 0; i < 4; ++i)
            #pragma unroll
            for (int p = 0; p < 4; ++p) acc[i][p] = 0ull;

        gemm64(xs, wt, tx, ty, acc);

        #pragma unroll
        for (int i = 0; i < 4; ++i) {
            int row = ty + 16 * i;
            float* qrow = qs + row * QS_STRIDE;
            #pragma unroll
            for (int p = 0; p < 4; ++p) {
                int n0 = tx + 32 * p, n1 = n0 + 16;
                float f0, f1;
                unpack2(acc[i][p], f0, f1);
                f0 += __ldg(qkv_b + chunk * 128 + n0);
                f1 += __ldg(qkv_b + chunk * 128 + n1);
                if (chunk == 0) {
                    qrow[n0] = f0;
                    qrow[n1] = f1;
                } else if (chunk == 1) {
                    *(float2*)(qrow + 128 + 2 * n0) = make_float2(f0, f0);
                    *(float2*)(qrow + 128 + 2 * n1) = make_float2(f1, f1);
                } else {
                    qrow[384 + n0] = f0;
                    qrow[384 + n1] = f1;
                }
            }
        }
    }
    __syncthreads();

    // conv weight load overlaps attention (wt region free now)
    load_w(conv_w, wt, t);

    // ---------------- phase 3: attention ----------------
    unsigned long long pm = 0ull;
    if (bz == 7 || by == 15 || bx == 31) {
        #pragma unroll
        for (int m = 0; m < 64; ++m) {
            bool p = (bz == 7 && (m >> 4) >= 2) ||
                     (by == 15 && ((m >> 2) & 3) >= 2) ||
                     (bx == 31 && (m & 3) >= 2);
            pm |= (unsigned long long)(p ? 1u : 0u) << m;
        }
    }

    const int head = t >> 5;
    const int lane = t & 31;
    const int r0 = lane, r1 = lane + 32;
    const unsigned p0 = (unsigned)(pm >> r0) & 1u;
    const unsigned p1 = (unsigned)(pm >> r1) & 1u;

    // packed q pairs: qp[d] = (q_r0[d], q_r1[d])
    u64 qp[16];
    {
        const float4* q0p = (const float4*)(qs + r0 * QS_STRIDE + head * 16);
        const float4* q1p = (const float4*)(qs + r1 * QS_STRIDE + head * 16);
        #pragma unroll
        for (int w4 = 0; w4 < 4; ++w4) {
            float4 a = q0p[w4], b = q1p[w4];
            qp[4 * w4 + 0] = pack2(a.x, b.x);
            qp[4 * w4 + 1] = pack2(a.y, b.y);
            qp[4 * w4 + 2] = pack2(a.z, b.z);
            qp[4 * w4 + 3] = pack2(a.w, b.w);
        }
    }

    u64 acc0[8], acc1[8];
    #pragma unroll
    for (int j = 0; j < 8; ++j) { acc0[j] = 0ull; acc1[j] = 0ull; }
    float sum0 = 0.f, sum1 = 0.f;

    #pragma unroll 2
    for (int m = 0; m < 64; ++m) {
        const ulonglong2* kd = (const ulonglong2*)(qs + m * QS_STRIDE + 128 + head * 32);
        ulonglong2 kk = kd[0];
        u64 sp = fmul2(qp[0], kk.x);
        sp = ffma2(qp[1], kk.y, sp);
        #pragma unroll
        for (int j = 1; j < 8; ++j) {
            kk = kd[j];
            sp = ffma2(qp[2 * j],     kk.x, sp);
            sp = ffma2(qp[2 * j + 1], kk.y, sp);
        }
        float s0, s1;
        unpack2(sp, s0, s1);

        unsigned pmm = (unsigned)(pm >> m) & 1u;
        float e0 = (pmm == p0) ? __expf(s0 * 0.25f) : 0.f;
        float e1 = (pmm == p1) ? __expf(s1 * 0.25f) : 0.f;
        sum0 += e0;
        sum1 += e1;
        u64 pe0 = pack2(e0, e0);
        u64 pe1 = pack2(e1, e1);

        const ulonglong2* vp = (const ulonglong2*)(qs + m * QS_STRIDE + 384 + head * 16);
        #pragma unroll
        for (int j = 0; j < 4; ++j) {
            ulonglong2 vv = vp[j];
            acc0[2 * j]     = ffma2(pe0, vv.x, acc0[2 * j]);
            acc0[2 * j + 1] = ffma2(pe0, vv.y, acc0[2 * j + 1]);
            acc1[2 * j]     = ffma2(pe1, vv.x, acc1[2 * j]);
            acc1[2 * j + 1] = ffma2(pe1, vv.y, acc1[2 * j + 1]);
        }
    }

    {
        float inv0 = 1.0f / sum0;
        float inv1 = 1.0f / sum1;
        u64 pi0 = pack2(inv0, inv0);
        u64 pi1 = pack2(inv1, inv1);
        u64* y0 = (u64*)(xs + r0 * XS_STRIDE + head * 16);
        u64* y1 = (u64*)(xs + r1 * XS_STRIDE + head * 16);
        #pragma unroll
        for (int j = 0; j < 8; ++j) {
            y0[j] = fmul2(acc0[j], pi0);
            y1[j] = fmul2(acc1[j], pi1);
        }
    }
    __syncthreads();   // y_s and conv wt both ready

    // ---------------- phase 4: 1x1 conv GEMM ----------------
    u64 cacc[4][4];
    #pragma unroll
    for (int i = 0; i < 4; ++i)
        #pragma unroll
        for (int p = 0; p < 4; ++p) cacc[i][p] = 0ull;

    gemm64(xs, wt, tx, ty, cacc);

    #pragma unroll
    for (int i = 0; i < 4; ++i) {
        int m  = ty + 16 * i;
        int gz = z0 + (m >> 4);
        int gy = y0 + ((m >> 2) & 3);
        int gx = x0 + (m & 3);
        if (gz < D0 && gy < H0 && gx < W0) {
            size_t vaddr = (size_t)(gz * H0 + gy) * W0 + gx;
            #pragma unroll
            for (int p = 0; p < 4; ++p) {
                int o0 = tx + 32 * p, o1 = o0 + 16;
                float f0, f1;
                unpack2(cacc[i][p], f0, f1);
                out[(size_t)o0 * MTOT + vaddr] = f0 + __ldg(conv_b + o0);
                out[(size_t)o1 * MTOT + vaddr] = f1 + __ldg(conv_b + o1);
            }
        }
    }
}

extern "C" void kernel_launch(void* const* d_in, const int* in_sizes, int n_in,
                              void* d_out, int out_size)
{
    const float* x      = (const float*)d_in[0];
    const float* qkv_w  = (const float*)d_in[1];
    const float* qkv_b  = (const float*)d_in[2];
    const float* conv_w = (const float*)d_in[3];
    const float* conv_b = (const float*)d_in[4];
    float* out = (float*)d_out;

    cudaFuncSetAttribute(fused_window_attn_kernel,
                         cudaFuncAttributeMaxDynamicSharedMemorySize,
                         SMEM_FLOATS * (int)sizeof(float));

    fused_window_attn_kernel<<<4096, 256, SMEM_FLOATS * sizeof(float)>>>(
        x, qkv_w, qkv_b, conv_w, conv_b, out);
}